// round 1
// baseline (speedup 1.0000x reference)
#include <cuda_runtime.h>
#include <math.h>

#define BN 4
#define CN 64
#define HN 128
#define WN 128
#define HW (HN*WN)

// ---------------- scratch (device globals; no allocation allowed) ----------------
__device__ float g_xt [BN*HW*CN];      // x in NHWC: [((b*H+h)*W+w)*64 + c]
__device__ float g_off[BN*HW*27];      // per pixel: 9 taps * (dy, dx, sigmoid(mask))
__device__ float g_w1t[9*64*27];       // offset conv W: [(tap*64+c)*27 + oc]
__device__ float g_w2t[64*576];        // dcn W: [( (kc>>2)*64 + o )*4 + (kc&3)], kc = k*64+c

// ---------------- kernel 0: weight re-layout ----------------
__global__ void prep_weights(const float* __restrict__ w1, const float* __restrict__ w2) {
    int stride = gridDim.x * blockDim.x;
    int tid = blockIdx.x * blockDim.x + threadIdx.x;
    // offset conv weights: src [oc][c][ky][kx] (27,64,3,3)
    for (int s = tid; s < 27*576; s += stride) {
        int oc = s / 576;
        int r  = s % 576;
        int c  = r / 9;
        int t  = r % 9;
        g_w1t[(t*64 + c)*27 + oc] = w1[s];
    }
    // dcn weights: src [o][c][ky][kx] (64,64,3,3)
    for (int s = tid; s < 64*576; s += stride) {
        int o = s / 576;
        int r = s % 576;
        int c = r / 9;
        int t = r % 9;
        int kc = t*64 + c;
        g_w2t[((kc >> 2)*64 + o)*4 + (kc & 3)] = w2[s];
    }
}

// ---------------- kernel 1: NCHW -> NHWC transpose of x ----------------
__global__ void transpose_x(const float* __restrict__ x) {
    __shared__ float tile[32][33];
    int b  = blockIdx.z;
    int s0 = blockIdx.x * 32;   // spatial
    int c0 = blockIdx.y * 32;   // channel
    int tx = threadIdx.x, ty = threadIdx.y;  // (32, 8)
    const float* xb = x + (size_t)b * CN * HW;
    #pragma unroll
    for (int j = 0; j < 4; j++) {
        int c = c0 + ty + j*8;
        tile[ty + j*8][tx] = xb[(size_t)c*HW + s0 + tx];
    }
    __syncthreads();
    float* ob = g_xt + (size_t)b * HW * CN;
    #pragma unroll
    for (int j = 0; j < 4; j++) {
        int s = s0 + ty + j*8;
        ob[(size_t)s*CN + c0 + tx] = tile[tx][ty + j*8];
    }
}

// ---------------- kernel 2: offset conv (3x3, 64 -> 27) ----------------
// block: (32,8) = 256 thr; tile: 4 rows x 8 cols of output pixels.
// threadIdx.x = out channel (27 active); threadIdx.y = pixel group (4 pixels, same row).
__global__ void offset_conv(const float* __restrict__ bias) {
    __shared__ float4 xs[6*10*16];   // [( (r)*10 + col )*16 + c4] halo tile, NHWC
    int b  = blockIdx.z;
    int h0 = blockIdx.y * 4;
    int w0 = blockIdx.x * 8;
    int tid = threadIdx.y * 32 + threadIdx.x;

    const float4* xt4 = (const float4*)g_xt + (size_t)b * HW * 16;
    for (int idx = tid; idx < 960; idx += 256) {
        int c4  = idx & 15;
        int rc  = idx >> 4;
        int col = rc % 10;
        int r   = rc / 10;
        int gh = h0 - 1 + r;
        int gw = w0 - 1 + col;
        float4 v = make_float4(0.f, 0.f, 0.f, 0.f);
        if (gh >= 0 && gh < HN && gw >= 0 && gw < WN)
            v = xt4[((size_t)gh*WN + gw)*16 + c4];
        xs[idx] = v;
    }
    __syncthreads();

    int oc = threadIdx.x;
    if (oc >= 27) return;
    int g = threadIdx.y;
    int prow = g >> 1;            // pixel row in tile (0..3)
    int pcb  = (g & 1) * 4;       // pixel col base (0 or 4)

    float acc0 = 0.f, acc1 = 0.f, acc2 = 0.f, acc3 = 0.f;

    for (int t = 0; t < 9; t++) {
        int ky = t / 3, kx = t % 3;
        const float4* xrow = &xs[((prow + ky)*10 + pcb + kx)*16];
        const float* wt = g_w1t + t*64*27 + oc;
        #pragma unroll
        for (int c4 = 0; c4 < 16; c4++) {
            float wa = __ldg(wt + (c4*4 + 0)*27);
            float wb = __ldg(wt + (c4*4 + 1)*27);
            float wc = __ldg(wt + (c4*4 + 2)*27);
            float wd = __ldg(wt + (c4*4 + 3)*27);
            float4 v0 = xrow[c4];
            float4 v1 = xrow[16 + c4];
            float4 v2 = xrow[32 + c4];
            float4 v3 = xrow[48 + c4];
            acc0 += v0.x*wa + v0.y*wb + v0.z*wc + v0.w*wd;
            acc1 += v1.x*wa + v1.y*wb + v1.z*wc + v1.w*wd;
            acc2 += v2.x*wa + v2.y*wb + v2.z*wc + v2.w*wd;
            acc3 += v3.x*wa + v3.y*wb + v3.z*wc + v3.w*wd;
        }
    }

    // channel -> (tap, component) shuffle + sigmoid for masks
    // offset channel c comes from conv channel (c<9 ? c : c+9); masks are conv 9..17
    float bv = __ldg(bias + oc);
    int slot;
    bool sig = false;
    if (oc < 9) {
        slot = (oc >> 1)*3 + (oc & 1);
    } else if (oc < 18) {
        slot = (oc - 9)*3 + 2;
        sig = true;
    } else {
        int c = oc - 9;
        slot = (c >> 1)*3 + (c & 1);
    }
    int hh = h0 + prow;
    float accs[4] = {acc0, acc1, acc2, acc3};
    #pragma unroll
    for (int i = 0; i < 4; i++) {
        float v = accs[i] + bv;
        if (sig) v = 1.f / (1.f + expf(-v));
        int ww = w0 + pcb + i;
        g_off[((size_t)b*HW + hh*WN + ww)*27 + slot] = v;
    }
}

// ---------------- kernel 3: deformable conv ----------------
// block = 32 consecutive pixels (same b, same h) x 64 out channels, 512 threads.
// smem: dcn weights (147456 B) + val[32][576] (73728 B) = 221184 B dynamic.
#define DEF_SMEM (36864*4 + 18432*4)

__global__ void __launch_bounds__(512, 1) deform_kernel(const float* __restrict__ bias,
                                                        float* __restrict__ out) {
    extern __shared__ float sm[];
    float* w_s   = sm;            // 36864 floats
    float* val_s = sm + 36864;    // 18432 floats  (reused as out staging)

    int tid = threadIdx.x;

    // stage dcn weights into smem
    {
        float4* ws4 = (float4*)w_s;
        const float4* gw4 = (const float4*)g_w2t;
        for (int i = tid; i < 9216; i += 512) ws4[i] = gw4[i];
    }

    int g0  = blockIdx.x << 5;      // first pixel (global linear over B*H*W)
    int b   = g0 >> 14;             // /16384
    int rem = g0 & (HW - 1);
    int h   = rem >> 7;             // /128
    int w0  = rem & 127;

    // ---- Phase A: bilinear sampling into val_s[p][k*64 + c] ----
    int lane = tid & 31;
    int warp = tid >> 5;
    int c2   = lane << 1;
    const float* xb = g_xt + (size_t)b * HW * CN;

    for (int task = warp; task < 288; task += 16) {
        int p  = task / 9;
        int k  = task - p*9;
        int ky = k / 3;
        int kx = k - ky*3;
        int ww = w0 + p;
        size_t pix = (size_t)b*HW + h*WN + ww;
        const float* trip = g_off + pix*27 + k*3;
        float dy = __ldg(trip);
        float dx = __ldg(trip + 1);
        float m  = __ldg(trip + 2);

        float py = (float)(h - 1 + ky) + dy;
        float px = (float)(ww - 1 + kx) + dx;
        float fy = floorf(py), fx = floorf(px);
        int y0 = (int)fy, x0 = (int)fx;
        float ly = py - fy, lx = px - fx;
        float hy = 1.f - ly, hx = 1.f - lx;

        bool vy0 = (y0 >= 0)     && (y0 < HN);
        bool vy1 = (y0 + 1 >= 0) && (y0 + 1 < HN);
        bool vx0 = (x0 >= 0)     && (x0 < WN);
        bool vx1 = (x0 + 1 >= 0) && (x0 + 1 < WN);

        float2 v00 = make_float2(0.f, 0.f), v01 = v00, v10 = v00, v11 = v00;
        if (vy0 && vx0) v00 = *(const float2*)(xb + ((size_t)y0*WN + x0      )*64 + c2);
        if (vy0 && vx1) v01 = *(const float2*)(xb + ((size_t)y0*WN + x0 + 1  )*64 + c2);
        if (vy1 && vx0) v10 = *(const float2*)(xb + ((size_t)(y0+1)*WN + x0  )*64 + c2);
        if (vy1 && vx1) v11 = *(const float2*)(xb + ((size_t)(y0+1)*WN + x0+1)*64 + c2);

        float w00 = hy*hx*m, w01 = hy*lx*m, w10 = ly*hx*m, w11 = ly*lx*m;
        float2 r;
        r.x = w00*v00.x + w01*v01.x + w10*v10.x + w11*v11.x;
        r.y = w00*v00.y + w01*v01.y + w10*v10.y + w11*v11.y;
        *(float2*)(val_s + p*576 + k*64 + c2) = r;
    }
    __syncthreads();

    // ---- Phase B: out[p][o] = W(64x576) @ val[p] ----
    int o   = tid & 63;
    int grp = tid >> 6;             // 8 groups x 4 pixels
    float bv = __ldg(bias + o);

    const float4* vp0 = (const float4*)(val_s + (grp*4 + 0)*576);
    const float4* vp1 = (const float4*)(val_s + (grp*4 + 1)*576);
    const float4* vp2 = (const float4*)(val_s + (grp*4 + 2)*576);
    const float4* vp3 = (const float4*)(val_s + (grp*4 + 3)*576);
    const float4* wp  = (const float4*)w_s + o;

    float acc0 = 0.f, acc1 = 0.f, acc2 = 0.f, acc3 = 0.f;
    #pragma unroll 4
    for (int j = 0; j < 144; j++) {
        float4 wv = wp[j*64];
        float4 a = vp0[j];
        float4 bb = vp1[j];
        float4 c = vp2[j];
        float4 d = vp3[j];
        acc0 += a.x*wv.x + a.y*wv.y + a.z*wv.z + a.w*wv.w;
        acc1 += bb.x*wv.x + bb.y*wv.y + bb.z*wv.z + bb.w*wv.w;
        acc2 += c.x*wv.x + c.y*wv.y + c.z*wv.z + c.w*wv.w;
        acc3 += d.x*wv.x + d.y*wv.y + d.z*wv.z + d.w*wv.w;
    }
    float r0 = acc0 + bv, r1 = acc1 + bv, r2 = acc2 + bv, r3 = acc3 + bv;

    // ---- stage to smem for coalesced NCHW store ----
    __syncthreads();                // all val_s reads done
    float* out_s = val_s;           // reuse (needs 2048 floats)
    out_s[o*32 + grp*4 + 0] = r0;
    out_s[o*32 + grp*4 + 1] = r1;
    out_s[o*32 + grp*4 + 2] = r2;
    out_s[o*32 + grp*4 + 3] = r3;
    __syncthreads();

    float* ob = out + (size_t)b*64*HW + h*WN + w0;
    #pragma unroll
    for (int seg = 0; seg < 4; seg++) {
        int lin = seg*512 + tid;
        int oo  = lin >> 5;
        int pp  = lin & 31;
        ob[(size_t)oo*HW + pp] = out_s[lin];
    }
}

// ---------------- launch ----------------
extern "C" void kernel_launch(void* const* d_in, const int* in_sizes, int n_in,
                              void* d_out, int out_size) {
    const float* x  = (const float*)d_in[0];
    const float* w1 = (const float*)d_in[1];
    const float* b1 = (const float*)d_in[2];
    const float* w2 = (const float*)d_in[3];
    const float* b2 = (const float*)d_in[4];
    float* out = (float*)d_out;

    cudaFuncSetAttribute(deform_kernel, cudaFuncAttributeMaxDynamicSharedMemorySize, DEF_SMEM);

    prep_weights<<<64, 256>>>(w1, w2);
    transpose_x<<<dim3(HW/32, CN/32, BN), dim3(32, 8)>>>(x);
    offset_conv<<<dim3(WN/8, HN/4, BN), dim3(32, 8)>>>(b1);
    deform_kernel<<<(BN*HW)/32, 512, DEF_SMEM>>>(b2, out);
}

// round 3
// speedup vs baseline: 2.0256x; 2.0256x over previous
#include <cuda_runtime.h>
#include <cuda_bf16.h>
#include <math.h>
#include <stdint.h>

#define BN 4
#define CN 64
#define HN 128
#define WN 128
#define HW (HN*WN)

// ---------------- scratch (device globals) ----------------
__device__ float g_xt [BN*HW*CN];                 // x in NHWC
__device__ float g_off[BN*HW*27];                 // per pixel: 9 taps * (dy, dx, sigmoid(mask))
__device__ float g_w1t[9*64*27];                  // offset conv W: [(tap*64+c)*27 + oc]
// dcn weights as bf16 hi/lo, padded rows: [tap][hi/lo][64 oc][72 k] (72 = 64 + 8 pad)
__device__ __align__(16) unsigned short g_w2s[9*2*64*72];

// ---------------- helpers ----------------
__device__ __forceinline__ uint32_t smem_u32(const void* p) {
    uint32_t a;
    asm("{ .reg .u64 t; cvta.to.shared.u64 t, %1; cvt.u32.u64 %0, t; }" : "=r"(a) : "l"(p));
    return a;
}

__device__ __forceinline__ void lda4(uint32_t* r, uint32_t a) {
    asm volatile("ldmatrix.sync.aligned.m8n8.x4.shared.b16 {%0,%1,%2,%3}, [%4];"
        : "=r"(r[0]), "=r"(r[1]), "=r"(r[2]), "=r"(r[3]) : "r"(a));
}

__device__ __forceinline__ void mma16816(float* d, const uint32_t* a, uint32_t b0, uint32_t b1) {
    asm volatile("mma.sync.aligned.m16n8k16.row.col.f32.bf16.bf16.f32 "
        "{%0,%1,%2,%3}, {%4,%5,%6,%7}, {%8,%9}, {%0,%1,%2,%3};"
        : "+f"(d[0]), "+f"(d[1]), "+f"(d[2]), "+f"(d[3])
        : "r"(a[0]), "r"(a[1]), "r"(a[2]), "r"(a[3]), "r"(b0), "r"(b1));
}

// ---------------- kernel 0: weight re-layout ----------------
__global__ void prep_weights(const float* __restrict__ w1, const float* __restrict__ w2) {
    int stride = gridDim.x * blockDim.x;
    int tid = blockIdx.x * blockDim.x + threadIdx.x;
    // offset conv weights: src [oc][c][ky][kx] (27,64,3,3)
    for (int s = tid; s < 27*576; s += stride) {
        int oc = s / 576;
        int r  = s % 576;
        int c  = r / 9;
        int t  = r % 9;
        g_w1t[(t*64 + c)*27 + oc] = w1[s];
    }
    // dcn weights: src [o][c][ky][kx] -> bf16 hi/lo at [t][p][o][c] (rows padded to 72)
    for (int s = tid; s < 64*576; s += stride) {
        int o = s / 576;
        int r = s % 576;
        int c = r / 9;
        int t = r % 9;
        float w = w2[s];
        __nv_bfloat16 hi = __float2bfloat16_rn(w);
        __nv_bfloat16 lo = __float2bfloat16_rn(w - __bfloat162float(hi));
        unsigned short* base = g_w2s + (size_t)t * (2*64*72);
        base[o*72 + c]          = *(unsigned short*)&hi;
        base[64*72 + o*72 + c]  = *(unsigned short*)&lo;
    }
    // zero the pad columns (never read by ldmatrix, but keep deterministic)
    for (int s = tid; s < 9*2*64*8; s += stride) {
        int row = s / 8;
        int pc  = s % 8;
        g_w2s[row*72 + 64 + pc] = 0;
    }
}

// ---------------- kernel 1: NCHW -> NHWC transpose of x ----------------
__global__ void transpose_x(const float* __restrict__ x) {
    __shared__ float tile[32][33];
    int b  = blockIdx.z;
    int s0 = blockIdx.x * 32;
    int c0 = blockIdx.y * 32;
    int tx = threadIdx.x, ty = threadIdx.y;
    const float* xb = x + (size_t)b * CN * HW;
    #pragma unroll
    for (int j = 0; j < 4; j++) {
        int c = c0 + ty + j*8;
        tile[ty + j*8][tx] = xb[(size_t)c*HW + s0 + tx];
    }
    __syncthreads();
    float* ob = g_xt + (size_t)b * HW * CN;
    #pragma unroll
    for (int j = 0; j < 4; j++) {
        int s = s0 + ty + j*8;
        ob[(size_t)s*CN + c0 + tx] = tile[tx][ty + j*8];
    }
}

// ---------------- kernel 2: offset conv (3x3, 64 -> 27) ----------------
__global__ void offset_conv(const float* __restrict__ bias) {
    __shared__ float4 xs[6*10*16];
    int b  = blockIdx.z;
    int h0 = blockIdx.y * 4;
    int w0 = blockIdx.x * 8;
    int tid = threadIdx.y * 32 + threadIdx.x;

    const float4* xt4 = (const float4*)g_xt + (size_t)b * HW * 16;
    for (int idx = tid; idx < 960; idx += 256) {
        int c4  = idx & 15;
        int rc  = idx >> 4;
        int col = rc % 10;
        int r   = rc / 10;
        int gh = h0 - 1 + r;
        int gw = w0 - 1 + col;
        float4 v = make_float4(0.f, 0.f, 0.f, 0.f);
        if (gh >= 0 && gh < HN && gw >= 0 && gw < WN)
            v = xt4[((size_t)gh*WN + gw)*16 + c4];
        xs[idx] = v;
    }
    __syncthreads();

    int oc = threadIdx.x;
    if (oc >= 27) return;
    int g = threadIdx.y;
    int prow = g >> 1;
    int pcb  = (g & 1) * 4;

    float acc0 = 0.f, acc1 = 0.f, acc2 = 0.f, acc3 = 0.f;

    for (int t = 0; t < 9; t++) {
        int ky = t / 3, kx = t % 3;
        const float4* xrow = &xs[((prow + ky)*10 + pcb + kx)*16];
        const float* wt = g_w1t + t*64*27 + oc;
        #pragma unroll
        for (int c4 = 0; c4 < 16; c4++) {
            float wa = __ldg(wt + (c4*4 + 0)*27);
            float wb = __ldg(wt + (c4*4 + 1)*27);
            float wc = __ldg(wt + (c4*4 + 2)*27);
            float wd = __ldg(wt + (c4*4 + 3)*27);
            float4 v0 = xrow[c4];
            float4 v1 = xrow[16 + c4];
            float4 v2 = xrow[32 + c4];
            float4 v3 = xrow[48 + c4];
            acc0 += v0.x*wa + v0.y*wb + v0.z*wc + v0.w*wd;
            acc1 += v1.x*wa + v1.y*wb + v1.z*wc + v1.w*wd;
            acc2 += v2.x*wa + v2.y*wb + v2.z*wc + v2.w*wd;
            acc3 += v3.x*wa + v3.y*wb + v3.z*wc + v3.w*wd;
        }
    }

    float bv = __ldg(bias + oc);
    int slot;
    bool sig = false;
    if (oc < 9) {
        slot = (oc >> 1)*3 + (oc & 1);
    } else if (oc < 18) {
        slot = (oc - 9)*3 + 2;
        sig = true;
    } else {
        int c = oc - 9;
        slot = (c >> 1)*3 + (c & 1);
    }
    int hh = h0 + prow;
    float accs[4] = {acc0, acc1, acc2, acc3};
    #pragma unroll
    for (int i = 0; i < 4; i++) {
        float v = accs[i] + bv;
        if (sig) v = 1.f / (1.f + expf(-v));
        int ww = w0 + pcb + i;
        g_off[((size_t)b*HW + hh*WN + ww)*27 + slot] = v;
    }
}

// ---------------- kernel 3: deformable conv via mma.sync bf16x3 ----------------
// CTA = one image row: M = 128 px, N = 64 oc, K = 576. 256 threads (8 warps, 4m x 2n).
// smem (dynamic, 110592 B -> 2 CTAs/SM):
//   VAL: 2 bufs x (hi [128][72]bf16 + lo) = 2 x 36864
//   WT : 2 bufs x (hi [64][72]bf16 + lo)  = 2 x 18432
#define VAL_OFF 0
#define VBUF    36864
#define WT_OFF  73728
#define WBUF    18432
#define DT_SMEM 110592

__global__ void __launch_bounds__(256, 2) deform_mma(const float* __restrict__ bias,
                                                     float* __restrict__ out) {
    extern __shared__ char sm[];
    uint32_t sbase = smem_u32(sm);
    int tid  = threadIdx.x;
    int lane = tid & 31;
    int warp = tid >> 5;

    int b = blockIdx.x >> 7;
    int h = blockIdx.x & 127;
    const float* xb   = g_xt + (size_t)b * HW * CN;
    const float* offp = g_off + ((size_t)b*HW + (size_t)h*WN) * 27;

    float D[2][4][4];
    #pragma unroll
    for (int i = 0; i < 2; i++)
        #pragma unroll
        for (int j = 0; j < 4; j++)
            #pragma unroll
            for (int q = 0; q < 4; q++) D[i][j][q] = 0.f;

    // ---- fill stage lambda-ish (macro by code dup): sample tap t into buf ----
    auto fill = [&](int t, int buf) {
        // stage weights for tap t
        {
            const uint4* src = (const uint4*)(g_w2s + (size_t)t * (2*64*72));
            uint4* dst = (uint4*)(sm + WT_OFF + buf*WBUF);
            for (int i = tid; i < 1152; i += 256) dst[i] = src[i];
        }
        // sample 16 px per warp
        int ky = t / 3, kx = t - ky*3;
        char* vHi = sm + VAL_OFF + buf*VBUF;
        char* vLo = vHi + 18432;
        int c2 = lane << 1;
        #pragma unroll 4
        for (int i = 0; i < 16; i++) {
            int px = (warp << 4) + i;
            const float* trip = offp + px*27 + t*3;
            float dy = __ldg(trip);
            float dx = __ldg(trip + 1);
            float m  = __ldg(trip + 2);

            float py  = (float)(h - 1 + ky) + dy;
            float pxx = (float)(px - 1 + kx) + dx;
            float fy = floorf(py), fx = floorf(pxx);
            int y0 = (int)fy, x0 = (int)fx;
            float ly = py - fy, lx = pxx - fx;
            float hy = 1.f - ly, hx = 1.f - lx;

            bool vy0 = (y0 >= 0)     && (y0 < HN);
            bool vy1 = (y0 + 1 >= 0) && (y0 + 1 < HN);
            bool vx0 = (x0 >= 0)     && (x0 < WN);
            bool vx1 = (x0 + 1 >= 0) && (x0 + 1 < WN);

            float2 v00 = make_float2(0.f,0.f), v01 = v00, v10 = v00, v11 = v00;
            if (vy0 && vx0) v00 = *(const float2*)(xb + ((size_t)y0*WN + x0      )*64 + c2);
            if (vy0 && vx1) v01 = *(const float2*)(xb + ((size_t)y0*WN + x0 + 1  )*64 + c2);
            if (vy1 && vx0) v10 = *(const float2*)(xb + ((size_t)(y0+1)*WN + x0  )*64 + c2);
            if (vy1 && vx1) v11 = *(const float2*)(xb + ((size_t)(y0+1)*WN + x0+1)*64 + c2);

            float w00 = hy*hx*m, w01 = hy*lx*m, w10 = ly*hx*m, w11 = ly*lx*m;
            float2 r;
            r.x = w00*v00.x + w01*v01.x + w10*v10.x + w11*v11.x;
            r.y = w00*v00.y + w01*v01.y + w10*v10.y + w11*v11.y;

            __nv_bfloat162 h2 = __float22bfloat162_rn(r);
            float2 rs = make_float2(r.x - __bfloat162float(h2.x),
                                    r.y - __bfloat162float(h2.y));
            __nv_bfloat162 l2 = __float22bfloat162_rn(rs);

            uint32_t off = (uint32_t)(px*144 + lane*4);
            *(__nv_bfloat162*)(vHi + off) = h2;
            *(__nv_bfloat162*)(vLo + off) = l2;
        }
    };

    // mma consume tap in buf
    int mwoff = (warp >> 1) * 32;   // m offset of this warp
    int nwoff = (warp & 1) * 32;    // n offset
    // A address components
    uint32_t aRowSel = (lane & 15);
    uint32_t aColSel = (lane >> 4) * 16;
    // B address components
    uint32_t bRowSel = ((lane >> 4) & 1) * 8 + (lane & 7);
    uint32_t bColSel = ((lane >> 3) & 1) * 16;

    auto consume = [&](int buf) {
        uint32_t vh = sbase + VAL_OFF + buf*VBUF;
        uint32_t vl = vh + 18432;
        uint32_t wh = sbase + WT_OFF + buf*WBUF;
        uint32_t wl = wh + 9216;
        #pragma unroll
        for (int ks = 0; ks < 4; ks++) {
            uint32_t Ah[2][4], Al[2][4], Bh[2][4], Bl[2][4];
            #pragma unroll
            for (int mb = 0; mb < 2; mb++) {
                uint32_t ao = (mwoff + mb*16 + aRowSel)*144 + ks*32 + aColSel;
                lda4(Ah[mb], vh + ao);
                lda4(Al[mb], vl + ao);
            }
            #pragma unroll
            for (int nb = 0; nb < 2; nb++) {
                uint32_t bo = (nwoff + nb*16 + bRowSel)*144 + ks*32 + bColSel;
                lda4(Bh[nb], wh + bo);
                lda4(Bl[nb], wl + bo);
            }
            #pragma unroll
            for (int mb = 0; mb < 2; mb++)
                #pragma unroll
                for (int nb = 0; nb < 2; nb++)
                    #pragma unroll
                    for (int nh = 0; nh < 2; nh++) {
                        float* dd = D[mb][nb*2 + nh];
                        mma16816(dd, Ah[mb], Bh[nb][nh*2], Bh[nb][nh*2+1]);
                        mma16816(dd, Al[mb], Bh[nb][nh*2], Bh[nb][nh*2+1]);
                        mma16816(dd, Ah[mb], Bl[nb][nh*2], Bl[nb][nh*2+1]);
                    }
        }
    };

    fill(0, 0);
    __syncthreads();
    for (int t = 0; t < 9; t++) {
        int buf = t & 1;
        if (t < 8) fill(t + 1, buf ^ 1);
        consume(buf);
        __syncthreads();
    }

    // ---- epilogue: D regs -> smem [oc][132 px] -> coalesced NCHW store ----
    float* out_s = (float*)sm;
    int lq = lane >> 2, lr = lane & 3;
    #pragma unroll
    for (int mb = 0; mb < 2; mb++) {
        #pragma unroll
        for (int ni = 0; ni < 4; ni++) {
            float* dd = D[mb][ni];
            int n0 = nwoff + ni*8 + 2*lr;
            int m0 = mwoff + mb*16 + lq;
            out_s[ n0     *132 + m0    ] = dd[0];
            out_s[(n0 + 1)*132 + m0    ] = dd[1];
            out_s[ n0     *132 + m0 + 8] = dd[2];
            out_s[(n0 + 1)*132 + m0 + 8] = dd[3];
        }
    }
    __syncthreads();

    float* ob = out + (size_t)b*64*HW + (size_t)h*WN;
    #pragma unroll
    for (int i = 0; i < 32; i++) {
        int lin = i*256 + tid;
        int oc = lin >> 7;
        int px = lin & 127;
        ob[(size_t)oc*HW + px] = out_s[oc*132 + px] + __ldg(bias + oc);
    }
}

// ---------------- launch ----------------
extern "C" void kernel_launch(void* const* d_in, const int* in_sizes, int n_in,
                              void* d_out, int out_size) {
    const float* x  = (const float*)d_in[0];
    const float* w1 = (const float*)d_in[1];
    const float* b1 = (const float*)d_in[2];
    const float* w2 = (const float*)d_in[3];
    const float* b2 = (const float*)d_in[4];
    float* out = (float*)d_out;

    cudaFuncSetAttribute(deform_mma, cudaFuncAttributeMaxDynamicSharedMemorySize, DT_SMEM);

    prep_weights<<<64, 256>>>(w1, w2);
    transpose_x<<<dim3(HW/32, CN/32, BN), dim3(32, 8)>>>(x);
    offset_conv<<<dim3(WN/8, HN/4, BN), dim3(32, 8)>>>(b1);
    deform_mma<<<BN*HN, 256, DT_SMEM>>>(b2, out);
}